// round 2
// baseline (speedup 1.0000x reference)
#include <cuda_runtime.h>

#define NB   16
#define NN   10000
#define NE   320000
#define CIN  32
#define COUT 64
#define CC   96            // CIN + COUT
#define BC   1536          // NB*CC  (features per node, conv layout)
#define MROWS 160000       // NN*NB

// ---------------- static scratch (no cudaMalloc allowed) ----------------
__device__ float g_feat[5][NN * BC];        // x0, x1f, x1b, x2f, x2b
__device__ float g_ru[MROWS * 128];         // sigmoid(ru): r = [:,0:64], u = [:,64:128]
__device__ float g_deg_f[NN], g_deg_b[NN];
__device__ int   g_cnt_f[NN], g_cnt_b[NN];
__device__ int   g_cur_f[NN], g_cur_b[NN];
__device__ int   g_rp_f[NN + 1], g_rp_b[NN + 1];
__device__ int2  g_csr_f[NE], g_csr_b[NE];  // (neighbor, weight-as-bits)
__device__ int   g_any_odd;                 // dtype sniff: 0 => edge_index is int64

// ---------------- edge-index accessors (int32 vs int64 robust) ----------------
__device__ __forceinline__ int load_node(const int* ei, int idx, int is64) {
    // is64: little-endian int64 values < 2^31  -> low word at 2*idx
    return is64 ? ei[2 * idx] : ei[idx];
}

// ---------------- small kernels ----------------
__global__ void zero_kernel() {
    int i = blockIdx.x * blockDim.x + threadIdx.x;
    if (i == 0) g_any_odd = 0;
    if (i < NN) {
        g_deg_f[i] = 0.f; g_deg_b[i] = 0.f;
        g_cnt_f[i] = 0;   g_cnt_b[i] = 0;
        g_cur_f[i] = 0;   g_cur_b[i] = 0;
    }
}

// Sample odd 32-bit words of the first 8192 words. All zero <=> int64 payload.
__global__ void detect_kernel(const int* __restrict__ ei) {
    int t = threadIdx.x;                     // 256 threads
    int any = 0;
    for (int j = 2 * t + 1; j < 8192; j += 512) any |= ei[j];
    // warp+block reduce via atomics (tiny)
    if (any) atomicOr(&g_any_odd, 1);
}

__global__ void deg_kernel(const int* __restrict__ ei,
                           const float* __restrict__ ew) {
    int e = blockIdx.x * blockDim.x + threadIdx.x;
    if (e >= NE) return;
    int is64 = (g_any_odd == 0);
    int s = load_node(ei, e, is64);
    int d = load_node(ei, NE + e, is64);
    float w = ew[e];
    atomicAdd(&g_deg_f[s], w);
    atomicAdd(&g_deg_b[d], w);
    atomicAdd(&g_cnt_f[d], 1);   // forward CSR grouped by dst
    atomicAdd(&g_cnt_b[s], 1);   // backward CSR grouped by src
}

// two exclusive scans (10000 elems each): block 0 -> forward, block 1 -> backward
__global__ void scan_kernel() {
    const int* cnt = (blockIdx.x == 0) ? g_cnt_f : g_cnt_b;
    int* rp        = (blockIdx.x == 0) ? g_rp_f  : g_rp_b;
    __shared__ int sm[1024];
    __shared__ int s_carry;
    if (threadIdx.x == 0) s_carry = 0;
    __syncthreads();
    for (int base = 0; base < NN; base += 1024) {
        int i = base + threadIdx.x;
        int v = (i < NN) ? cnt[i] : 0;
        sm[threadIdx.x] = v;
        __syncthreads();
        for (int ofs = 1; ofs < 1024; ofs <<= 1) {
            int t = (threadIdx.x >= ofs) ? sm[threadIdx.x - ofs] : 0;
            __syncthreads();
            sm[threadIdx.x] += t;
            __syncthreads();
        }
        int carry = s_carry;
        if (i < NN) rp[i] = carry + sm[threadIdx.x] - v;
        __syncthreads();
        if (threadIdx.x == 1023) s_carry = carry + sm[1023];
        __syncthreads();
    }
    if (threadIdx.x == 0) rp[NN] = s_carry;
}

__global__ void scatter_kernel(const int* __restrict__ ei,
                               const float* __restrict__ ew) {
    int e = blockIdx.x * blockDim.x + threadIdx.x;
    if (e >= NE) return;
    int is64 = (g_any_odd == 0);
    int s = load_node(ei, e, is64);
    int d = load_node(ei, NE + e, is64);
    float w = ew[e];
    float wf = w / g_deg_f[s];
    float wb = w / g_deg_b[d];
    int p = atomicAdd(&g_cur_f[d], 1);
    g_csr_f[g_rp_f[d] + p] = make_int2(s, __float_as_int(wf));
    int q = atomicAdd(&g_cur_b[s], 1);
    g_csr_b[g_rp_b[s] + q] = make_int2(d, __float_as_int(wb));
}

// feat0[n][b*96+c] = c<32 ? x[b,n,c] : h[b,n,c-32]
__global__ void build_feat0(const float* __restrict__ x,
                            const float* __restrict__ hs) {
    int idx = blockIdx.x * 256 + threadIdx.x;
    if (idx >= NN * BC) return;
    int n = idx / BC;
    int r = idx - n * BC;
    int b = r / CC;
    int c = r - b * CC;
    float v = (c < CIN) ? x[(b * NN + n) * CIN + c]
                        : hs[(b * NN + n) * COUT + (c - CIN)];
    g_feat[0][idx] = v;
}

// r*h into feat0 hidden slots (conv2 order-0 term)
__global__ void rh_kernel(const float* __restrict__ hs) {
    int idx = blockIdx.x * 256 + threadIdx.x;
    if (idx >= MROWS * COUT) return;
    int m = idx >> 6;       // n*16 + b
    int o = idx & 63;
    int n = m >> 4;
    int b = m & 15;
    float r = g_ru[m * 128 + o];
    float h = hs[(b * NN + n) * COUT + o];
    g_feat[0][n * BC + b * CC + CIN + o] = r * h;
}

// ---------------- propagation (gather segment-sum) ----------------
// out[node] = alpha * sum_{edges of node} w * in[nbr]   ( - base[node] if base_idx>=0 )
template <bool HONLY>
__global__ void prop_kernel(int in_idx, int out_idx, int base_idx, int fwd, float alpha) {
    const float* __restrict__ in  = g_feat[in_idx];
    float* __restrict__ out       = g_feat[out_idx];
    const int* __restrict__ rp    = fwd ? g_rp_f : g_rp_b;
    const int2* __restrict__ csr  = fwd ? g_csr_f : g_csr_b;

    int node = blockIdx.y;
    int t = blockIdx.x * 256 + threadIdx.x;
    int off;
    if (HONLY) off = (t >> 6) * CC + CIN + (t & 63);   // only hidden channels
    else       off = t;

    int s = rp[node];
    int e = rp[node + 1];
    float acc = 0.f;
    int i = s;
    for (; i + 3 < e; i += 4) {
        int2 e0 = __ldg(&csr[i]);
        int2 e1 = __ldg(&csr[i + 1]);
        int2 e2 = __ldg(&csr[i + 2]);
        int2 e3 = __ldg(&csr[i + 3]);
        float v0 = __ldg(&in[e0.x * BC + off]);
        float v1 = __ldg(&in[e1.x * BC + off]);
        float v2 = __ldg(&in[e2.x * BC + off]);
        float v3 = __ldg(&in[e3.x * BC + off]);
        acc += __int_as_float(e0.y) * v0;
        acc += __int_as_float(e1.y) * v1;
        acc += __int_as_float(e2.y) * v2;
        acc += __int_as_float(e3.y) * v3;
    }
    for (; i < e; ++i) {
        int2 ed = __ldg(&csr[i]);
        acc += __int_as_float(ed.y) * __ldg(&in[ed.x * BC + off]);
    }
    float v = alpha * acc;
    if (base_idx >= 0) v -= g_feat[base_idx][node * BC + off];
    out[node * BC + off] = v;
}

// ---------------- GEMM: out(M=160000, NOUT) = sum_l A_l(160000,96) @ W_l(96,NOUT) ----------------
// A_l = g_feat[l] viewed as (160000,96) row-major (n*16+b rows). W_l[c][o] = param[c*5+l][o].
template <int NOUT, bool ISRU>
__global__ void __launch_bounds__(256) gemm_kernel(const float* __restrict__ Wp,
                                                   const float* __restrict__ bias,
                                                   const float* __restrict__ hs,
                                                   float* __restrict__ dout) {
    constexpr int TX = (NOUT == 128) ? 16 : 8;
    constexpr int TY = 256 / TX;
    constexpr int MM = 128 / TY;      // rows per thread (8 or 4)

    __shared__ float As[128 * 20];    // As[row*20 + k]
    __shared__ float Bs[16 * NOUT];   // Bs[k*NOUT + col]

    const float* Aptr[5] = { g_feat[0], g_feat[1], g_feat[2], g_feat[3], g_feat[4] };

    int tid = threadIdx.x;
    int tx = tid % TX;
    int ty = tid / TX;
    int mBase = blockIdx.x * 128;

    float acc[MM][8];
#pragma unroll
    for (int i = 0; i < MM; i++)
#pragma unroll
        for (int j = 0; j < 8; j++) acc[i][j] = 0.f;

    for (int l = 0; l < 5; ++l) {
        const float* Asrc = Aptr[l];
        for (int k0 = 0; k0 < CC; k0 += 16) {
            // load A tile: 128 rows x 16 k = 512 float4
#pragma unroll
            for (int j = 0; j < 2; j++) {
                int fid = j * 256 + tid;
                int row = fid >> 2;
                int kq = fid & 3;
                float4 v = *reinterpret_cast<const float4*>(Asrc + (mBase + row) * CC + k0 + kq * 4);
                *reinterpret_cast<float4*>(&As[row * 20 + kq * 4]) = v;
            }
            // load B tile: 16 x NOUT
            constexpr int NB4 = 16 * NOUT / 4;
#pragma unroll
            for (int j = 0; j < (NB4 + 255) / 256; ++j) {
                int fid = j * 256 + tid;
                if (NB4 % 256 == 0 || fid < NB4) {
                    int krow = fid / (NOUT / 4);
                    int cq = fid % (NOUT / 4);
                    int c = k0 + krow;
                    float4 v = *reinterpret_cast<const float4*>(Wp + (c * 5 + l) * NOUT + cq * 4);
                    *reinterpret_cast<float4*>(&Bs[krow * NOUT + cq * 4]) = v;
                }
            }
            __syncthreads();
#pragma unroll
            for (int kt = 0; kt < 16; ++kt) {
                float a[MM];
#pragma unroll
                for (int i = 0; i < MM; i++) a[i] = As[(ty * MM + i) * 20 + kt];
                float4 b0 = *reinterpret_cast<const float4*>(&Bs[kt * NOUT + tx * 8]);
                float4 b1 = *reinterpret_cast<const float4*>(&Bs[kt * NOUT + tx * 8 + 4]);
                float bb[8] = { b0.x, b0.y, b0.z, b0.w, b1.x, b1.y, b1.z, b1.w };
#pragma unroll
                for (int i = 0; i < MM; i++)
#pragma unroll
                    for (int j = 0; j < 8; j++) acc[i][j] += a[i] * bb[j];
            }
            __syncthreads();
        }
    }

    // epilogue
#pragma unroll
    for (int i = 0; i < MM; i++) {
        int row = mBase + ty * MM + i;    // row = n*16 + b
#pragma unroll
        for (int j = 0; j < 8; j++) {
            int col = tx * 8 + j;
            float v = acc[i][j] + bias[col];
            if (ISRU) {
                g_ru[row * 128 + col] = 1.f / (1.f + expf(-v));
            } else {
                float cv = tanhf(tanhf(v));
                int n = row >> 4;
                int b = row & 15;
                float u = g_ru[row * 128 + 64 + col];
                float h = hs[(b * NN + n) * COUT + col];
                dout[(b * NN + n) * COUT + col] = u * h + (1.f - u) * cv;
            }
        }
    }
}

// ---------------- launch ----------------
extern "C" void kernel_launch(void* const* d_in, const int* in_sizes, int n_in,
                              void* d_out, int out_size) {
    const float* x        = (const float*)d_in[0];
    const float* hs       = (const float*)d_in[1];
    const int*   ei       = (const int*)d_in[2];
    const float* ew       = (const float*)d_in[3];
    const float* ru_param = (const float*)d_in[4];
    const float* ru_bias  = (const float*)d_in[5];
    const float* c_param  = (const float*)d_in[6];
    const float* c_bias   = (const float*)d_in[7];
    float* out = (float*)d_out;

    // graph preprocessing
    zero_kernel<<<(NN + 255) / 256, 256>>>();
    detect_kernel<<<1, 256>>>(ei);
    deg_kernel<<<(NE + 255) / 256, 256>>>(ei, ew);
    scan_kernel<<<2, 1024>>>();
    scatter_kernel<<<(NE + 255) / 256, 256>>>(ei, ew);

    // conv1 input features [x, h]
    build_feat0<<<(NN * BC + 255) / 256, 256>>>(x, hs);

    // conv1 Chebyshev propagations (full 1536 channels)
    dim3 gp_full(BC / 256, NN);
    prop_kernel<false><<<gp_full, 256>>>(0, 1, -1, 1, 1.f);   // x1f = Pf x0
    prop_kernel<false><<<gp_full, 256>>>(0, 2, -1, 0, 1.f);   // x1b = Pb x0
    prop_kernel<false><<<gp_full, 256>>>(1, 3,  0, 1, 2.f);   // x2f = 2 Pf x1f - x0
    prop_kernel<false><<<gp_full, 256>>>(2, 4,  0, 0, 2.f);   // x2b = 2 Pb x1b - x0

    // ru gates = sigmoid(cheb @ ru_param + bias)
    gemm_kernel<128, true><<<MROWS / 128, 256>>>(ru_param, ru_bias, nullptr, nullptr);

    // conv2 order-0 hidden part: r*h (x-part of all feat buffers reused from conv1)
    rh_kernel<<<(MROWS * COUT + 255) / 256, 256>>>(hs);

    // conv2 Chebyshev propagations (hidden 1024 channels only)
    dim3 gp_h(NB * COUT / 256, NN);
    prop_kernel<true><<<gp_h, 256>>>(0, 1, -1, 1, 1.f);
    prop_kernel<true><<<gp_h, 256>>>(0, 2, -1, 0, 1.f);
    prop_kernel<true><<<gp_h, 256>>>(1, 3,  0, 1, 2.f);
    prop_kernel<true><<<gp_h, 256>>>(2, 4,  0, 0, 2.f);

    // c = tanh(tanh(cheb @ c_param + bias));  out = u*h + (1-u)*c
    gemm_kernel<64, false><<<MROWS / 128, 256>>>(c_param, c_bias, hs, out);
}

// round 3
// speedup vs baseline: 1.1699x; 1.1699x over previous
#include <cuda_runtime.h>
#include <cstdint>

#define NB   16
#define NN   10000
#define NE   320000
#define CIN  32
#define COUT 64
#define CC   96            // CIN + COUT
#define BC   1536          // NB*CC  (features per node, conv layout)
#define MROWS 160000       // NN*NB

// ---------------- static scratch (no cudaMalloc allowed) ----------------
__device__ float g_feat[5][NN * BC];        // x0, x1f, x1b, x2f, x2b
__device__ float g_ru[MROWS * 128];         // sigmoid(ru): r = [:,0:64], u = [:,64:128]
__device__ float g_deg_f[NN], g_deg_b[NN];
__device__ int   g_cnt_f[NN], g_cnt_b[NN];
__device__ int   g_cur_f[NN], g_cur_b[NN];
__device__ int   g_rp_f[NN + 1], g_rp_b[NN + 1];
__device__ int2  g_csr_f[NE], g_csr_b[NE];  // (neighbor, weight-as-bits)
__device__ int   g_any_odd;                 // dtype sniff: 0 => edge_index is int64

__device__ __forceinline__ int load_node(const int* ei, int idx, int is64) {
    return is64 ? ei[2 * idx] : ei[idx];
}

__device__ __forceinline__ uint32_t f2tf(float x) {
    uint32_t r;
    asm("cvt.rna.tf32.f32 %0, %1;" : "=r"(r) : "f"(x));
    return r;
}

// ---------------- preprocessing kernels ----------------
__global__ void zero_detect_kernel(const int* __restrict__ ei) {
    int i = blockIdx.x * 256 + threadIdx.x;
    if (i < NN) {
        g_deg_f[i] = 0.f; g_deg_b[i] = 0.f;
        g_cnt_f[i] = 0;   g_cnt_b[i] = 0;
        g_cur_f[i] = 0;   g_cur_b[i] = 0;
    }
    if (blockIdx.x == 0) {
        __shared__ int s_any;
        if (threadIdx.x == 0) s_any = 0;
        __syncthreads();
        int any = 0;
        for (int j = 2 * threadIdx.x + 1; j < 8192; j += 512) any |= ei[j];
        if (any) atomicOr(&s_any, 1);
        __syncthreads();
        if (threadIdx.x == 0) g_any_odd = s_any;
    }
}

__global__ void deg_kernel(const int* __restrict__ ei,
                           const float* __restrict__ ew) {
    int e = blockIdx.x * blockDim.x + threadIdx.x;
    if (e >= NE) return;
    int is64 = (g_any_odd == 0);
    int s = load_node(ei, e, is64);
    int d = load_node(ei, NE + e, is64);
    float w = ew[e];
    atomicAdd(&g_deg_f[s], w);
    atomicAdd(&g_deg_b[d], w);
    atomicAdd(&g_cnt_f[d], 1);   // forward CSR grouped by dst
    atomicAdd(&g_cnt_b[s], 1);   // backward CSR grouped by src
}

__global__ void scan_kernel() {
    const int* cnt = (blockIdx.x == 0) ? g_cnt_f : g_cnt_b;
    int* rp        = (blockIdx.x == 0) ? g_rp_f  : g_rp_b;
    __shared__ int sm[1024];
    __shared__ int s_carry;
    if (threadIdx.x == 0) s_carry = 0;
    __syncthreads();
    for (int base = 0; base < NN; base += 1024) {
        int i = base + threadIdx.x;
        int v = (i < NN) ? cnt[i] : 0;
        sm[threadIdx.x] = v;
        __syncthreads();
        for (int ofs = 1; ofs < 1024; ofs <<= 1) {
            int t = (threadIdx.x >= ofs) ? sm[threadIdx.x - ofs] : 0;
            __syncthreads();
            sm[threadIdx.x] += t;
            __syncthreads();
        }
        int carry = s_carry;
        if (i < NN) rp[i] = carry + sm[threadIdx.x] - v;
        __syncthreads();
        if (threadIdx.x == 1023) s_carry = carry + sm[1023];
        __syncthreads();
    }
    if (threadIdx.x == 0) rp[NN] = s_carry;
}

__global__ void scatter_kernel(const int* __restrict__ ei,
                               const float* __restrict__ ew) {
    int e = blockIdx.x * blockDim.x + threadIdx.x;
    if (e >= NE) return;
    int is64 = (g_any_odd == 0);
    int s = load_node(ei, e, is64);
    int d = load_node(ei, NE + e, is64);
    float w = ew[e];
    float wf = w / g_deg_f[s];
    float wb = w / g_deg_b[d];
    int p = atomicAdd(&g_cur_f[d], 1);
    g_csr_f[g_rp_f[d] + p] = make_int2(s, __float_as_int(wf));
    int q = atomicAdd(&g_cur_b[s], 1);
    g_csr_b[g_rp_b[s] + q] = make_int2(d, __float_as_int(wb));
}

// feat0[n][b*96+c] = c<32 ? x[b,n,c] : h[b,n,c-32]
__global__ void build_feat0(const float* __restrict__ x,
                            const float* __restrict__ hs) {
    int idx = blockIdx.x * 256 + threadIdx.x;
    if (idx >= NN * BC) return;
    int n = idx / BC;
    int r = idx - n * BC;
    int b = r / CC;
    int c = r - b * CC;
    float v = (c < CIN) ? x[(b * NN + n) * CIN + c]
                        : hs[(b * NN + n) * COUT + (c - CIN)];
    g_feat[0][idx] = v;
}

// r*h into feat0 hidden slots (conv2 order-0 term)
__global__ void rh_kernel(const float* __restrict__ hs) {
    int idx = blockIdx.x * 256 + threadIdx.x;
    if (idx >= MROWS * COUT) return;
    int m = idx >> 6;       // n*16 + b
    int o = idx & 63;
    int n = m >> 4;
    int b = m & 15;
    float r = g_ru[m * 128 + o];
    float h = hs[(b * NN + n) * COUT + o];
    g_feat[0][n * BC + b * CC + CIN + o] = r * h;
}

// ---------------- propagation (gather segment-sum) ----------------
template <bool HONLY>
__global__ void prop_kernel(int in_idx, int out_idx, int base_idx, int fwd, float alpha) {
    const float* __restrict__ in  = g_feat[in_idx];
    float* __restrict__ out       = g_feat[out_idx];
    const int* __restrict__ rp    = fwd ? g_rp_f : g_rp_b;
    const int2* __restrict__ csr  = fwd ? g_csr_f : g_csr_b;

    int node = blockIdx.y;
    int t = blockIdx.x * 256 + threadIdx.x;
    int off;
    if (HONLY) off = (t >> 6) * CC + CIN + (t & 63);   // only hidden channels
    else       off = t;

    int s = rp[node];
    int e = rp[node + 1];
    float acc = 0.f;
    int i = s;
    for (; i + 3 < e; i += 4) {
        int2 e0 = __ldg(&csr[i]);
        int2 e1 = __ldg(&csr[i + 1]);
        int2 e2 = __ldg(&csr[i + 2]);
        int2 e3 = __ldg(&csr[i + 3]);
        float v0 = __ldg(&in[e0.x * BC + off]);
        float v1 = __ldg(&in[e1.x * BC + off]);
        float v2 = __ldg(&in[e2.x * BC + off]);
        float v3 = __ldg(&in[e3.x * BC + off]);
        acc += __int_as_float(e0.y) * v0;
        acc += __int_as_float(e1.y) * v1;
        acc += __int_as_float(e2.y) * v2;
        acc += __int_as_float(e3.y) * v3;
    }
    for (; i < e; ++i) {
        int2 ed = __ldg(&csr[i]);
        acc += __int_as_float(ed.y) * __ldg(&in[ed.x * BC + off]);
    }
    float v = alpha * acc;
    if (base_idx >= 0) v -= g_feat[base_idx][node * BC + off];
    out[node * BC + off] = v;
}

// ---------------- tensor-core GEMM (tf32 mma.sync.m16n8k8) ----------------
// out(M=160000, NOUT) = sum_l A_l(160000,96) @ W_l(96,NOUT)
// A_l = g_feat[l] as (MROWS, 96) row-major. W_l[k][o] = Wp[(k*5+l)*NOUT + o].
// Block: 256 thr = 8 warps (4 M-warps x 2 N-warps). Block tile 128 x NOUT.
// Warp tile 32 x NOUT/2. Fragments loaded straight from gmem (L1/L2 hot).
template <int NOUT, bool ISRU>
__global__ void __launch_bounds__(256) gemm_tc(const float* __restrict__ Wp,
                                               const float* __restrict__ bias,
                                               const float* __restrict__ hs,
                                               float* __restrict__ dout) {
    constexpr int WN = NOUT / 2;   // warp N extent
    constexpr int NF = WN / 8;     // n-fragments per warp (8 for ru, 4 for c)

    int tid  = threadIdx.x;
    int w    = tid >> 5;
    int lane = tid & 31;
    int wm   = w >> 1;            // 0..3
    int wn   = w & 1;             // 0..1
    int g    = lane >> 2;         // 0..7
    int t    = lane & 3;          // 0..3
    int mRow = blockIdx.x * 128 + wm * 32;

    float acc[2][NF][4];
#pragma unroll
    for (int mf = 0; mf < 2; mf++)
#pragma unroll
        for (int nf = 0; nf < NF; nf++)
#pragma unroll
            for (int j = 0; j < 4; j++) acc[mf][nf][j] = 0.f;

#pragma unroll 1
    for (int l = 0; l < 5; ++l) {
        const float* __restrict__ Al = g_feat[l];
        const float* __restrict__ Bl = Wp + l * NOUT;
#pragma unroll 2
        for (int k0 = 0; k0 < CC; k0 += 8) {
            // A fragments: a0=A[g][t], a1=A[g+8][t], a2=A[g][t+4], a3=A[g+8][t+4]
            uint32_t a[2][4];
#pragma unroll
            for (int mf = 0; mf < 2; mf++) {
                const float* ap = Al + (size_t)(mRow + mf * 16 + g) * CC + k0 + t;
                a[mf][0] = f2tf(__ldg(ap));
                a[mf][2] = f2tf(__ldg(ap + 4));
                a[mf][1] = f2tf(__ldg(ap + 8 * CC));
                a[mf][3] = f2tf(__ldg(ap + 8 * CC + 4));
            }
            // B fragments: b0=B[t][g], b1=B[t+4][g]  (B is k x n)
            uint32_t b[NF][2];
#pragma unroll
            for (int nf = 0; nf < NF; nf++) {
                int col = wn * WN + nf * 8 + g;
                const float* bp = Bl + (size_t)(k0 + t) * 5 * NOUT + col;
                b[nf][0] = f2tf(__ldg(bp));
                b[nf][1] = f2tf(__ldg(bp + 4 * 5 * NOUT));
            }
#pragma unroll
            for (int mf = 0; mf < 2; mf++)
#pragma unroll
                for (int nf = 0; nf < NF; nf++) {
                    asm volatile(
                        "mma.sync.aligned.m16n8k8.row.col.f32.tf32.tf32.f32 "
                        "{%0,%1,%2,%3}, {%4,%5,%6,%7}, {%8,%9}, {%0,%1,%2,%3};"
                        : "+f"(acc[mf][nf][0]), "+f"(acc[mf][nf][1]),
                          "+f"(acc[mf][nf][2]), "+f"(acc[mf][nf][3])
                        : "r"(a[mf][0]), "r"(a[mf][1]), "r"(a[mf][2]), "r"(a[mf][3]),
                          "r"(b[nf][0]), "r"(b[nf][1]));
                }
        }
    }

    // epilogue: d0=D[g][2t], d1=D[g][2t+1], d2=D[g+8][2t], d3=D[g+8][2t+1]
#pragma unroll
    for (int mf = 0; mf < 2; mf++) {
        int r0 = mRow + mf * 16 + g;
#pragma unroll
        for (int nf = 0; nf < NF; nf++) {
            int c0 = wn * WN + nf * 8 + 2 * t;
#pragma unroll
            for (int j = 0; j < 4; j++) {
                int row = r0 + (j >> 1) * 8;        // n*16 + b
                int col = c0 + (j & 1);
                float v = acc[mf][nf][j] + bias[col];
                if (ISRU) {
                    g_ru[(size_t)row * 128 + col] = 1.f / (1.f + expf(-v));
                } else {
                    float cv = tanhf(tanhf(v));
                    int n = row >> 4;
                    int b = row & 15;
                    float u = g_ru[(size_t)row * 128 + 64 + col];
                    float h = hs[(size_t)(b * NN + n) * COUT + col];
                    dout[(size_t)(b * NN + n) * COUT + col] = u * h + (1.f - u) * cv;
                }
            }
        }
    }
}

// ---------------- launch ----------------
extern "C" void kernel_launch(void* const* d_in, const int* in_sizes, int n_in,
                              void* d_out, int out_size) {
    const float* x        = (const float*)d_in[0];
    const float* hs       = (const float*)d_in[1];
    const int*   ei       = (const int*)d_in[2];
    const float* ew       = (const float*)d_in[3];
    const float* ru_param = (const float*)d_in[4];
    const float* ru_bias  = (const float*)d_in[5];
    const float* c_param  = (const float*)d_in[6];
    const float* c_bias   = (const float*)d_in[7];
    float* out = (float*)d_out;

    // graph preprocessing
    zero_detect_kernel<<<(NN + 255) / 256, 256>>>(ei);
    deg_kernel<<<(NE + 255) / 256, 256>>>(ei, ew);
    scan_kernel<<<2, 1024>>>();
    scatter_kernel<<<(NE + 255) / 256, 256>>>(ei, ew);

    // conv1 input features [x, h]
    build_feat0<<<(NN * BC + 255) / 256, 256>>>(x, hs);

    // conv1 Chebyshev propagations (full 1536 channels)
    dim3 gp_full(BC / 256, NN);
    prop_kernel<false><<<gp_full, 256>>>(0, 1, -1, 1, 1.f);   // x1f = Pf x0
    prop_kernel<false><<<gp_full, 256>>>(0, 2, -1, 0, 1.f);   // x1b = Pb x0
    prop_kernel<false><<<gp_full, 256>>>(1, 3,  0, 1, 2.f);   // x2f = 2 Pf x1f - x0
    prop_kernel<false><<<gp_full, 256>>>(2, 4,  0, 0, 2.f);   // x2b = 2 Pb x1b - x0

    // ru gates = sigmoid(cheb @ ru_param + bias)   [tensor cores]
    gemm_tc<128, true><<<MROWS / 128, 256>>>(ru_param, ru_bias, nullptr, nullptr);

    // conv2 order-0 hidden part: r*h (x-part of all feat buffers reused from conv1)
    rh_kernel<<<(MROWS * COUT + 255) / 256, 256>>>(hs);

    // conv2 Chebyshev propagations (hidden 1024 channels only)
    dim3 gp_h(NB * COUT / 256, NN);
    prop_kernel<true><<<gp_h, 256>>>(0, 1, -1, 1, 1.f);
    prop_kernel<true><<<gp_h, 256>>>(0, 2, -1, 0, 1.f);
    prop_kernel<true><<<gp_h, 256>>>(1, 3,  0, 1, 2.f);
    prop_kernel<true><<<gp_h, 256>>>(2, 4,  0, 0, 2.f);

    // c = tanh(tanh(cheb @ c_param + bias));  out = u*h + (1-u)*c   [tensor cores]
    gemm_tc<64, false><<<MROWS / 128, 256>>>(c_param, c_bias, hs, out);
}

// round 4
// speedup vs baseline: 1.5885x; 1.3578x over previous
#include <cuda_runtime.h>
#include <cuda_fp16.h>
#include <cstdint>

#define NB   16
#define NN   10000
#define NE   320000
#define CIN  32
#define COUT 64
#define CC   96            // CIN + COUT
#define BC   1536          // NB*CC  (features per node, conv layout)
#define BC2  768           // BC/2 (half2 pairs per node)
#define MROWS 160000       // NN*NB

#define DEG_BLOCKS  1250           // NE/256
#define FEAT_PAIRS  (NN * BC / 2)  // 7,680,000
#define FEAT_BLOCKS (FEAT_PAIRS / 256)

// ---------------- static scratch (no cudaMalloc; zero-init at load, re-zeroed at tail) ----------------
__device__ __half g_feat[5][NN * BC];       // x0, x1f, x1b, x2f, x2b  (fp16, 153.6MB)
__device__ float  g_ru[MROWS * 128];        // sigmoid(ru): r = [:,0:64], u = [:,64:128]
__device__ float  g_deg_f[NN], g_deg_b[NN];
__device__ int    g_cnt_f[NN], g_cnt_b[NN];
__device__ int    g_cur_f[NN], g_cur_b[NN];
__device__ int    g_rp_f[NN + 1], g_rp_b[NN + 1];
__device__ int2   g_csr_f[NE], g_csr_b[NE]; // (neighbor, weight-as-bits)
__device__ int    g_any_odd;                // dtype sniff: 0 => edge_index is int64

__device__ __forceinline__ int load_node(const int* ei, int idx, int is64) {
    return is64 ? ei[2 * idx] : ei[idx];   // little-endian int64 low word
}

__device__ __forceinline__ uint32_t f2tf(float x) {
    uint32_t r;
    asm("cvt.rna.tf32.f32 %0, %1;" : "=r"(r) : "f"(x));
    return r;
}

// ---------------- fused preprocessing: deg/cnt (+dtype detect) || build feat0 ----------------
// blocks [0, DEG_BLOCKS): edge degree/count accumulation
// blocks [DEG_BLOCKS, DEG_BLOCKS+FEAT_BLOCKS): feat0[n][b*96+c] = c<32 ? x : h  (fp16)
__global__ void pre_kernel(const int* __restrict__ ei, const float* __restrict__ ew,
                           const float* __restrict__ x, const float* __restrict__ hs) {
    if (blockIdx.x < DEG_BLOCKS) {
        // per-block dtype self-detect on a fixed window (deterministic, L2-hot)
        __shared__ int s_any;
        if (threadIdx.x == 0) s_any = 0;
        __syncthreads();
        int any = 0;
        for (int j = 2 * threadIdx.x + 1; j < 8192; j += 512) any |= ei[j];
        if (any) atomicOr(&s_any, 1);
        __syncthreads();
        int is64 = (s_any == 0);
        if (blockIdx.x == 0 && threadIdx.x == 0) g_any_odd = s_any;  // for scatter

        int e = blockIdx.x * 256 + threadIdx.x;   // always < NE (grid exact)
        int s = load_node(ei, e, is64);
        int d = load_node(ei, NE + e, is64);
        float w = ew[e];
        atomicAdd(&g_deg_f[s], w);
        atomicAdd(&g_deg_b[d], w);
        atomicAdd(&g_cnt_f[d], 1);   // forward CSR grouped by dst
        atomicAdd(&g_cnt_b[s], 1);   // backward CSR grouped by src
    } else {
        int p = (blockIdx.x - DEG_BLOCKS) * 256 + threadIdx.x;  // pair index
        int n = p / BC2;
        int rem = p - n * BC2;
        int c = 2 * rem;             // channel within node row
        int b = c / CC;
        int cc = c - b * CC;         // even; cc and cc+1 in same region
        float v0, v1;
        if (cc < CIN) {
            const float* xp = x + (size_t)(b * NN + n) * CIN + cc;
            v0 = xp[0]; v1 = xp[1];
        } else {
            const float* hp = hs + (size_t)(b * NN + n) * COUT + (cc - CIN);
            v0 = hp[0]; v1 = hp[1];
        }
        reinterpret_cast<__half2*>(g_feat[0])[p] = __float22half2_rn(make_float2(v0, v1));
    }
}

// two exclusive scans (10000 elems each)
__global__ void scan_kernel() {
    const int* cnt = (blockIdx.x == 0) ? g_cnt_f : g_cnt_b;
    int* rp        = (blockIdx.x == 0) ? g_rp_f  : g_rp_b;
    __shared__ int sm[1024];
    __shared__ int s_carry;
    if (threadIdx.x == 0) s_carry = 0;
    __syncthreads();
    for (int base = 0; base < NN; base += 1024) {
        int i = base + threadIdx.x;
        int v = (i < NN) ? cnt[i] : 0;
        sm[threadIdx.x] = v;
        __syncthreads();
        for (int ofs = 1; ofs < 1024; ofs <<= 1) {
            int t = (threadIdx.x >= ofs) ? sm[threadIdx.x - ofs] : 0;
            __syncthreads();
            sm[threadIdx.x] += t;
            __syncthreads();
        }
        int carry = s_carry;
        if (i < NN) rp[i] = carry + sm[threadIdx.x] - v;
        __syncthreads();
        if (threadIdx.x == 1023) s_carry = carry + sm[1023];
        __syncthreads();
    }
    if (threadIdx.x == 0) rp[NN] = s_carry;
}

__global__ void scatter_kernel(const int* __restrict__ ei,
                               const float* __restrict__ ew) {
    int e = blockIdx.x * blockDim.x + threadIdx.x;
    if (e >= NE) return;
    int is64 = (g_any_odd == 0);
    int s = load_node(ei, e, is64);
    int d = load_node(ei, NE + e, is64);
    float w = ew[e];
    float wf = w / g_deg_f[s];
    float wb = w / g_deg_b[d];
    int p = atomicAdd(&g_cur_f[d], 1);
    g_csr_f[g_rp_f[d] + p] = make_int2(s, __float_as_int(wf));
    int q = atomicAdd(&g_cur_b[s], 1);
    g_csr_b[g_rp_b[s] + q] = make_int2(d, __float_as_int(wb));
}

// r*h into feat0 hidden slots (conv2 order-0 term), half2 granularity
__global__ void rh_kernel(const float* __restrict__ hs) {
    int j = blockIdx.x * 256 + threadIdx.x;    // pair index over MROWS*32
    if (j >= MROWS * 32) return;
    int m = j >> 5;        // n*16 + b
    int ow = j & 31;       // half2 pair within 64 h-channels
    int n = m >> 4;
    int b = m & 15;
    float2 r = *reinterpret_cast<const float2*>(&g_ru[(size_t)m * 128 + 2 * ow]);
    float2 h = *reinterpret_cast<const float2*>(&hs[(size_t)(b * NN + n) * COUT + 2 * ow]);
    reinterpret_cast<__half2*>(g_feat[0])[(size_t)n * BC2 + b * 48 + 16 + ow] =
        __float22half2_rn(make_float2(r.x * h.x, r.y * h.y));
}

// ---------------- propagation (gather segment-sum, fp16 payload, fp32 accum) ----------------
// out[node] = alpha * sum_{edges} w * in[nbr]  ( - base[node] if base_idx>=0 )
template <bool HONLY>
__global__ void prop_kernel(int in_idx, int out_idx, int base_idx, int fwd, float alpha) {
    const __half2* __restrict__ in  = reinterpret_cast<const __half2*>(g_feat[in_idx]);
    __half2* __restrict__ out       = reinterpret_cast<__half2*>(g_feat[out_idx]);
    const int* __restrict__ rp      = fwd ? g_rp_f : g_rp_b;
    const int2* __restrict__ csr    = fwd ? g_csr_f : g_csr_b;

    int node = blockIdx.y;
    int q = blockIdx.x * 256 + threadIdx.x;
    int p;                                        // half2 pair offset within node row
    if (HONLY) p = (q >> 5) * 48 + 16 + (q & 31); // hidden channels only
    else       p = q;

    int s = rp[node];
    int e = rp[node + 1];
    float ax = 0.f, ay = 0.f;
    int i = s;
    for (; i + 3 < e; i += 4) {
        int2 e0 = __ldg(&csr[i]);
        int2 e1 = __ldg(&csr[i + 1]);
        int2 e2 = __ldg(&csr[i + 2]);
        int2 e3 = __ldg(&csr[i + 3]);
        float2 v0 = __half22float2(__ldg(&in[(size_t)e0.x * BC2 + p]));
        float2 v1 = __half22float2(__ldg(&in[(size_t)e1.x * BC2 + p]));
        float2 v2 = __half22float2(__ldg(&in[(size_t)e2.x * BC2 + p]));
        float2 v3 = __half22float2(__ldg(&in[(size_t)e3.x * BC2 + p]));
        float w0 = __int_as_float(e0.y), w1 = __int_as_float(e1.y);
        float w2 = __int_as_float(e2.y), w3 = __int_as_float(e3.y);
        ax += w0 * v0.x + w1 * v1.x + w2 * v2.x + w3 * v3.x;
        ay += w0 * v0.y + w1 * v1.y + w2 * v2.y + w3 * v3.y;
    }
    for (; i < e; ++i) {
        int2 ed = __ldg(&csr[i]);
        float w = __int_as_float(ed.y);
        float2 v = __half22float2(__ldg(&in[(size_t)ed.x * BC2 + p]));
        ax += w * v.x;
        ay += w * v.y;
    }
    float rx = alpha * ax, ry = alpha * ay;
    if (base_idx >= 0) {
        float2 b = __half22float2(
            reinterpret_cast<const __half2*>(g_feat[base_idx])[(size_t)node * BC2 + p]);
        rx -= b.x; ry -= b.y;
    }
    out[(size_t)node * BC2 + p] = __float22half2_rn(make_float2(rx, ry));
}

// ---------------- tensor-core GEMM (tf32 mma, fp16 A storage) ----------------
// out(M=160000, NOUT) = sum_l A_l(160000,96) @ W_l(96,NOUT)
template <int NOUT, bool ISRU>
__global__ void __launch_bounds__(256) gemm_tc(const float* __restrict__ Wp,
                                               const float* __restrict__ bias,
                                               const float* __restrict__ hs,
                                               float* __restrict__ dout) {
    constexpr int WN = NOUT / 2;
    constexpr int NF = WN / 8;

    int tid  = threadIdx.x;
    int w    = tid >> 5;
    int lane = tid & 31;
    int wm   = w >> 1;
    int wn   = w & 1;
    int g    = lane >> 2;
    int t    = lane & 3;
    int mRow = blockIdx.x * 128 + wm * 32;

    float acc[2][NF][4];
#pragma unroll
    for (int mf = 0; mf < 2; mf++)
#pragma unroll
        for (int nf = 0; nf < NF; nf++)
#pragma unroll
            for (int j = 0; j < 4; j++) acc[mf][nf][j] = 0.f;

#pragma unroll 1
    for (int l = 0; l < 5; ++l) {
        const __half* __restrict__ Al = g_feat[l];
        const float* __restrict__ Bl = Wp + l * NOUT;
#pragma unroll 2
        for (int k0 = 0; k0 < CC; k0 += 8) {
            uint32_t a[2][4];
#pragma unroll
            for (int mf = 0; mf < 2; mf++) {
                const __half* ap = Al + (size_t)(mRow + mf * 16 + g) * CC + k0 + t;
                // fp16 -> f32 is exact and fp16 values are exactly representable in tf32
                a[mf][0] = __float_as_uint(__half2float(__ldg(ap)));
                a[mf][2] = __float_as_uint(__half2float(__ldg(ap + 4)));
                a[mf][1] = __float_as_uint(__half2float(__ldg(ap + 8 * CC)));
                a[mf][3] = __float_as_uint(__half2float(__ldg(ap + 8 * CC + 4)));
            }
            uint32_t b[NF][2];
#pragma unroll
            for (int nf = 0; nf < NF; nf++) {
                int col = wn * WN + nf * 8 + g;
                const float* bp = Bl + (size_t)(k0 + t) * 5 * NOUT + col;
                b[nf][0] = f2tf(__ldg(bp));
                b[nf][1] = f2tf(__ldg(bp + 4 * 5 * NOUT));
            }
#pragma unroll
            for (int mf = 0; mf < 2; mf++)
#pragma unroll
                for (int nf = 0; nf < NF; nf++) {
                    asm volatile(
                        "mma.sync.aligned.m16n8k8.row.col.f32.tf32.tf32.f32 "
                        "{%0,%1,%2,%3}, {%4,%5,%6,%7}, {%8,%9}, {%0,%1,%2,%3};"
                        : "+f"(acc[mf][nf][0]), "+f"(acc[mf][nf][1]),
                          "+f"(acc[mf][nf][2]), "+f"(acc[mf][nf][3])
                        : "r"(a[mf][0]), "r"(a[mf][1]), "r"(a[mf][2]), "r"(a[mf][3]),
                          "r"(b[nf][0]), "r"(b[nf][1]));
                }
        }
    }

#pragma unroll
    for (int mf = 0; mf < 2; mf++) {
        int r0 = mRow + mf * 16 + g;
#pragma unroll
        for (int nf = 0; nf < NF; nf++) {
            int c0 = wn * WN + nf * 8 + 2 * t;
#pragma unroll
            for (int j = 0; j < 4; j++) {
                int row = r0 + (j >> 1) * 8;        // n*16 + b
                int col = c0 + (j & 1);
                float v = acc[mf][nf][j] + bias[col];
                if (ISRU) {
                    g_ru[(size_t)row * 128 + col] = 1.f / (1.f + expf(-v));
                } else {
                    float cv = tanhf(tanhf(v));
                    int n = row >> 4;
                    int b = row & 15;
                    float u = g_ru[(size_t)row * 128 + 64 + col];
                    float h = hs[(size_t)(b * NN + n) * COUT + col];
                    dout[(size_t)(b * NN + n) * COUT + col] = u * h + (1.f - u) * cv;
                }
            }
        }
    }
}

// tail reset so the next kernel_launch call sees zeroed accumulators
__global__ void zero_tail_kernel() {
    int i = blockIdx.x * blockDim.x + threadIdx.x;
    if (i < NN) {
        g_deg_f[i] = 0.f; g_deg_b[i] = 0.f;
        g_cnt_f[i] = 0;   g_cnt_b[i] = 0;
        g_cur_f[i] = 0;   g_cur_b[i] = 0;
    }
}

// ---------------- launch ----------------
extern "C" void kernel_launch(void* const* d_in, const int* in_sizes, int n_in,
                              void* d_out, int out_size) {
    const float* x        = (const float*)d_in[0];
    const float* hs       = (const float*)d_in[1];
    const int*   ei       = (const int*)d_in[2];
    const float* ew       = (const float*)d_in[3];
    const float* ru_param = (const float*)d_in[4];
    const float* ru_bias  = (const float*)d_in[5];
    const float* c_param  = (const float*)d_in[6];
    const float* c_bias   = (const float*)d_in[7];
    float* out = (float*)d_out;

    // 1-3: preprocessing (arrays are zero at entry: static init / previous tail)
    pre_kernel<<<DEG_BLOCKS + FEAT_BLOCKS, 256>>>(ei, ew, x, hs);
    scan_kernel<<<2, 1024>>>();
    scatter_kernel<<<DEG_BLOCKS, 256>>>(ei, ew);

    // 4-7: conv1 Chebyshev propagations (full 1536 channels = 768 pairs)
    dim3 gp_full(BC2 / 256, NN);
    prop_kernel<false><<<gp_full, 256>>>(0, 1, -1, 1, 1.f);   // x1f = Pf x0
    prop_kernel<false><<<gp_full, 256>>>(0, 2, -1, 0, 1.f);   // x1b = Pb x0
    prop_kernel<false><<<gp_full, 256>>>(1, 3,  0, 1, 2.f);   // x2f = 2 Pf x1f - x0
    prop_kernel<false><<<gp_full, 256>>>(2, 4,  0, 0, 2.f);   // x2b = 2 Pb x1b - x0

    // ru gates = sigmoid(cheb @ ru_param + bias)
    gemm_tc<128, true><<<MROWS / 128, 256>>>(ru_param, ru_bias, nullptr, nullptr);

    // conv2 order-0 hidden part: r*h (x-part of feat buffers reused from conv1)
    rh_kernel<<<(MROWS * 32 + 255) / 256, 256>>>(hs);

    // conv2 Chebyshev propagations (hidden 1024 channels = 512 pairs)
    dim3 gp_h(2, NN);
    prop_kernel<true><<<gp_h, 256>>>(0, 1, -1, 1, 1.f);
    prop_kernel<true><<<gp_h, 256>>>(0, 2, -1, 0, 1.f);
    prop_kernel<true><<<gp_h, 256>>>(1, 3,  0, 1, 2.f);
    prop_kernel<true><<<gp_h, 256>>>(2, 4,  0, 0, 2.f);

    // c = tanh(tanh(cheb @ c_param + bias));  out = u*h + (1-u)*c
    gemm_tc<64, false><<<MROWS / 128, 256>>>(c_param, c_bias, hs, out);

    // reset accumulators for the next call
    zero_tail_kernel<<<(NN + 255) / 256, 256>>>();
}

// round 5
// speedup vs baseline: 3.5119x; 2.2109x over previous
#include <cuda_runtime.h>
#include <cuda_fp16.h>
#include <cstdint>

#define NB   16
#define NN   10000
#define NE   320000
#define CIN  32
#define COUT 64
#define CC   96            // CIN + COUT
#define BC   1536          // NB*CC  (features per node, conv layout)
#define BC2  768           // half2 pairs per node row
#define BC4  192           // int4 per node row
#define MROWS 160000       // NN*NB

#define DEG_BLOCKS  1250           // NE/256
#define FEAT_PAIRS  (NN * BC / 2)
#define FEAT_BLOCKS (FEAT_PAIRS / 256)

// ---------------- static scratch (zero-init at load, re-zeroed at tail) ----------------
__device__ __align__(16) __half g_feat[5][NN * BC];   // x0, x1f, x1b, x2f, x2b (fp16)
__device__ float  g_ru[MROWS * 128];        // sigmoid(ru): r=[:,0:64], u=[:,64:128]
__device__ float  g_deg_f[NN], g_deg_b[NN];
__device__ int    g_cnt_f[NN], g_cnt_b[NN];
__device__ int    g_cur_f[NN], g_cur_b[NN];
__device__ int    g_rp_f[NN + 1], g_rp_b[NN + 1];
__device__ int2   g_csr_f[NE], g_csr_b[NE]; // (neighbor, weight-as-bits)
__device__ int    g_any_odd;                // dtype sniff: 0 => edge_index is int64

__device__ __forceinline__ int load_node(const int* ei, int idx, int is64) {
    return is64 ? ei[2 * idx] : ei[idx];   // little-endian int64 low word
}

// ---------------- fused preprocessing: deg/cnt (+dtype detect) || build feat0 ----------------
__global__ void pre_kernel(const int* __restrict__ ei, const float* __restrict__ ew,
                           const float* __restrict__ x, const float* __restrict__ hs) {
    if (blockIdx.x < DEG_BLOCKS) {
        __shared__ int s_any;
        if (threadIdx.x == 0) s_any = 0;
        __syncthreads();
        int any = 0;
        for (int j = 2 * threadIdx.x + 1; j < 8192; j += 512) any |= ei[j];
        if (any) atomicOr(&s_any, 1);
        __syncthreads();
        int is64 = (s_any == 0);
        if (blockIdx.x == 0 && threadIdx.x == 0) g_any_odd = s_any;

        int e = blockIdx.x * 256 + threadIdx.x;
        int s = load_node(ei, e, is64);
        int d = load_node(ei, NE + e, is64);
        float w = ew[e];
        atomicAdd(&g_deg_f[s], w);
        atomicAdd(&g_deg_b[d], w);
        atomicAdd(&g_cnt_f[d], 1);
        atomicAdd(&g_cnt_b[s], 1);
    } else {
        int p = (blockIdx.x - DEG_BLOCKS) * 256 + threadIdx.x;  // half2 pair index
        int n = p / BC2;
        int rem = p - n * BC2;
        int c = 2 * rem;
        int b = c / CC;
        int cc = c - b * CC;
        float v0, v1;
        if (cc < CIN) {
            const float* xp = x + (size_t)(b * NN + n) * CIN + cc;
            v0 = xp[0]; v1 = xp[1];
        } else {
            const float* hp = hs + (size_t)(b * NN + n) * COUT + (cc - CIN);
            v0 = hp[0]; v1 = hp[1];
        }
        reinterpret_cast<__half2*>(g_feat[0])[p] = __float22half2_rn(make_float2(v0, v1));
    }
}

__global__ void scan_kernel() {
    const int* cnt = (blockIdx.x == 0) ? g_cnt_f : g_cnt_b;
    int* rp        = (blockIdx.x == 0) ? g_rp_f  : g_rp_b;
    __shared__ int sm[1024];
    __shared__ int s_carry;
    if (threadIdx.x == 0) s_carry = 0;
    __syncthreads();
    for (int base = 0; base < NN; base += 1024) {
        int i = base + threadIdx.x;
        int v = (i < NN) ? cnt[i] : 0;
        sm[threadIdx.x] = v;
        __syncthreads();
        for (int ofs = 1; ofs < 1024; ofs <<= 1) {
            int t = (threadIdx.x >= ofs) ? sm[threadIdx.x - ofs] : 0;
            __syncthreads();
            sm[threadIdx.x] += t;
            __syncthreads();
        }
        int carry = s_carry;
        if (i < NN) rp[i] = carry + sm[threadIdx.x] - v;
        __syncthreads();
        if (threadIdx.x == 1023) s_carry = carry + sm[1023];
        __syncthreads();
    }
    if (threadIdx.x == 0) rp[NN] = s_carry;
}

__global__ void scatter_kernel(const int* __restrict__ ei,
                               const float* __restrict__ ew) {
    int e = blockIdx.x * blockDim.x + threadIdx.x;
    if (e >= NE) return;
    int is64 = (g_any_odd == 0);
    int s = load_node(ei, e, is64);
    int d = load_node(ei, NE + e, is64);
    float w = ew[e];
    float wf = w / g_deg_f[s];
    float wb = w / g_deg_b[d];
    int p = atomicAdd(&g_cur_f[d], 1);
    g_csr_f[g_rp_f[d] + p] = make_int2(s, __float_as_int(wf));
    int q = atomicAdd(&g_cur_b[s], 1);
    g_csr_b[g_rp_b[s] + q] = make_int2(d, __float_as_int(wb));
}

// r*h into feat0 hidden slots (conv2 order-0 term)
__global__ void rh_kernel(const float* __restrict__ hs) {
    int j = blockIdx.x * 256 + threadIdx.x;    // pair index over MROWS*32
    if (j >= MROWS * 32) return;
    int m = j >> 5;        // n*16 + b
    int ow = j & 31;
    int n = m >> 4;
    int b = m & 15;
    float2 r = *reinterpret_cast<const float2*>(&g_ru[(size_t)m * 128 + 2 * ow]);
    float2 h = *reinterpret_cast<const float2*>(&hs[(size_t)(b * NN + n) * COUT + 2 * ow]);
    reinterpret_cast<__half2*>(g_feat[0])[(size_t)n * BC2 + b * 48 + 16 + ow] =
        __float22half2_rn(make_float2(r.x * h.x, r.y * h.y));
}

// ---------------- propagation: 8 channels/thread, fwd+bwd fused via blockIdx.y ----------------
__device__ __forceinline__ void acc8(float* a, int4 v, float w) {
    const __half2* h = reinterpret_cast<const __half2*>(&v);
#pragma unroll
    for (int q = 0; q < 4; q++) {
        float2 f = __half22float2(h[q]);
        a[2 * q]     += w * f.x;
        a[2 * q + 1] += w * f.y;
    }
}

// stage 0: out[1+dir] = P_dir feat0           (alpha=1, no base)
// stage 1: out[3+dir] = 2 P_dir feat[1+dir] - feat0
template <bool HONLY>
__global__ void __launch_bounds__(192) prop_pair(int stage) {
    int dir = blockIdx.y;                      // 0 = fwd, 1 = bwd
    int in_idx  = (stage == 0) ? 0 : 1 + dir;
    int out_idx = (stage == 0) ? 1 + dir : 3 + dir;
    float alpha = (stage == 0) ? 1.f : 2.f;

    const int4* __restrict__ in  = reinterpret_cast<const int4*>(g_feat[in_idx]);
    int4* __restrict__ out       = reinterpret_cast<int4*>(g_feat[out_idx]);
    const int* __restrict__ rp   = dir ? g_rp_b : g_rp_f;
    const int2* __restrict__ csr = dir ? g_csr_b : g_csr_f;

    int node = blockIdx.x;
    int t = threadIdx.x;
    int idx = HONLY ? ((t >> 3) * 12 + 4 + (t & 7)) : t;   // int4 within node row

    int s = rp[node];
    int e = rp[node + 1];
    float a[8];
#pragma unroll
    for (int q = 0; q < 8; q++) a[q] = 0.f;

    int i = s;
    for (; i + 1 < e; i += 2) {
        int2 e0 = __ldg(&csr[i]);
        int2 e1 = __ldg(&csr[i + 1]);
        int4 v0 = __ldg(&in[(size_t)e0.x * BC4 + idx]);
        int4 v1 = __ldg(&in[(size_t)e1.x * BC4 + idx]);
        acc8(a, v0, __int_as_float(e0.y));
        acc8(a, v1, __int_as_float(e1.y));
    }
    if (i < e) {
        int2 ed = __ldg(&csr[i]);
        int4 v = __ldg(&in[(size_t)ed.x * BC4 + idx]);
        acc8(a, v, __int_as_float(ed.y));
    }

    if (stage == 1) {
        int4 bv = reinterpret_cast<const int4*>(g_feat[0])[(size_t)node * BC4 + idx];
        const __half2* h = reinterpret_cast<const __half2*>(&bv);
#pragma unroll
        for (int q = 0; q < 4; q++) {
            float2 f = __half22float2(h[q]);
            a[2 * q]     = alpha * a[2 * q]     - f.x;
            a[2 * q + 1] = alpha * a[2 * q + 1] - f.y;
        }
    }
    int4 ov;
    __half2* oh = reinterpret_cast<__half2*>(&ov);
#pragma unroll
    for (int q = 0; q < 4; q++)
        oh[q] = __float22half2_rn(make_float2(a[2 * q], a[2 * q + 1]));
    out[(size_t)node * BC4 + idx] = ov;
}

// ---------------- tensor-core GEMM: fp16 mma.m16n8k16, fp32 accumulate ----------------
// out(M=160000, NOUT) = sum_l A_l(160000,96) @ W_l(96,NOUT)
// A_l = g_feat[l] as (MROWS,96) fp16 row-major; W_l[k][o] = Wp[(k*5+l)*NOUT+o] fp32.
// Block 128 rows x NOUT, 8 warps (4 M x 2 N), warp tile 32 x NOUT/2.
template <int NOUT, bool ISRU>
__global__ void __launch_bounds__(256) gemm_tc(const float* __restrict__ Wp,
                                               const float* __restrict__ bias,
                                               const float* __restrict__ hs,
                                               float* __restrict__ dout) {
    constexpr int WN = NOUT / 2;
    constexpr int NF = WN / 8;
    constexpr int ASTRIDE = 104;   // halves per A smem row (52 words, 16B-aligned)
    constexpr int BSTRIDE = 102;   // halves per B smem row (51 words, coprime bank step)

    __shared__ __align__(16) __half As[128 * ASTRIDE];
    __shared__ __align__(4)  __half Bs[NOUT * BSTRIDE];

    int tid  = threadIdx.x;
    int w    = tid >> 5;
    int lane = tid & 31;
    int wm   = w >> 1;
    int wn   = w & 1;
    int g    = lane >> 2;
    int t    = lane & 3;
    int mRow = blockIdx.x * 128;

    const uint32_t* Aw = reinterpret_cast<const uint32_t*>(As);
    const uint32_t* Bw = reinterpret_cast<const uint32_t*>(Bs);

    float acc[2][NF][4];
#pragma unroll
    for (int mf = 0; mf < 2; mf++)
#pragma unroll
        for (int nf = 0; nf < NF; nf++)
#pragma unroll
            for (int j = 0; j < 4; j++) acc[mf][nf][j] = 0.f;

#pragma unroll 1
    for (int l = 0; l < 5; ++l) {
        __syncthreads();   // previous tile fully consumed
        // A tile: 128 rows x 96 halves = 1536 int4, coalesced
        const int4* Ag = reinterpret_cast<const int4*>(g_feat[l]) + (size_t)mRow * 12;
#pragma unroll
        for (int j = 0; j < 6; j++) {
            int id = j * 256 + tid;
            int r = id / 12, c = id % 12;
            *reinterpret_cast<int4*>(&As[r * ASTRIDE + c * 8]) = __ldg(&Ag[r * 12 + c]);
        }
        // B tile transposed: Bs[n][k] = W_l[k][n], fp32 -> fp16
        {
            constexpr int KSTEP = 256 / NOUT;
            int n = tid % NOUT;
            int kb = tid / NOUT;
#pragma unroll
            for (int k = kb; k < CC; k += KSTEP)
                Bs[n * BSTRIDE + k] = __float2half(__ldg(&Wp[((size_t)k * 5 + l) * NOUT + n]));
        }
        __syncthreads();

#pragma unroll
        for (int ks = 0; ks < 6; ks++) {        // k0 = 16*ks
            uint32_t a[2][4];
#pragma unroll
            for (int mf = 0; mf < 2; mf++) {
                int base = (wm * 32 + mf * 16 + g) * (ASTRIDE / 2) + ks * 8 + t;
                a[mf][0] = Aw[base];
                a[mf][1] = Aw[base + 8 * (ASTRIDE / 2)];
                a[mf][2] = Aw[base + 4];
                a[mf][3] = Aw[base + 8 * (ASTRIDE / 2) + 4];
            }
            uint32_t b[NF][2];
#pragma unroll
            for (int nf = 0; nf < NF; nf++) {
                int col = wn * WN + nf * 8 + g;
                int bb = col * (BSTRIDE / 2) + ks * 8 + t;
                b[nf][0] = Bw[bb];
                b[nf][1] = Bw[bb + 4];
            }
#pragma unroll
            for (int mf = 0; mf < 2; mf++)
#pragma unroll
                for (int nf = 0; nf < NF; nf++) {
                    asm volatile(
                        "mma.sync.aligned.m16n8k16.row.col.f32.f16.f16.f32 "
                        "{%0,%1,%2,%3}, {%4,%5,%6,%7}, {%8,%9}, {%0,%1,%2,%3};"
                        : "+f"(acc[mf][nf][0]), "+f"(acc[mf][nf][1]),
                          "+f"(acc[mf][nf][2]), "+f"(acc[mf][nf][3])
                        : "r"(a[mf][0]), "r"(a[mf][1]), "r"(a[mf][2]), "r"(a[mf][3]),
                          "r"(b[nf][0]), "r"(b[nf][1]));
                }
        }
    }

    // epilogue: c0=D[g,2t], c1=D[g,2t+1], c2=D[g+8,2t], c3=D[g+8,2t+1]
#pragma unroll
    for (int mf = 0; mf < 2; mf++) {
        int r0 = mRow + wm * 32 + mf * 16 + g;
#pragma unroll
        for (int nf = 0; nf < NF; nf++) {
            int c0 = wn * WN + nf * 8 + 2 * t;
#pragma unroll
            for (int j = 0; j < 4; j++) {
                int row = r0 + (j >> 1) * 8;        // n*16 + b
                int col = c0 + (j & 1);
                float v = acc[mf][nf][j] + bias[col];
                if (ISRU) {
                    g_ru[(size_t)row * 128 + col] = 1.f / (1.f + expf(-v));
                } else {
                    float cv = tanhf(tanhf(v));
                    int n = row >> 4;
                    int b = row & 15;
                    float u = g_ru[(size_t)row * 128 + 64 + col];
                    float h = hs[(size_t)(b * NN + n) * COUT + col];
                    dout[(size_t)(b * NN + n) * COUT + col] = u * h + (1.f - u) * cv;
                }
            }
        }
    }
}

// tail reset so the next kernel_launch call sees zeroed accumulators
__global__ void zero_tail_kernel() {
    int i = blockIdx.x * blockDim.x + threadIdx.x;
    if (i < NN) {
        g_deg_f[i] = 0.f; g_deg_b[i] = 0.f;
        g_cnt_f[i] = 0;   g_cnt_b[i] = 0;
        g_cur_f[i] = 0;   g_cur_b[i] = 0;
    }
}

// ---------------- launch ----------------
extern "C" void kernel_launch(void* const* d_in, const int* in_sizes, int n_in,
                              void* d_out, int out_size) {
    const float* x        = (const float*)d_in[0];
    const float* hs       = (const float*)d_in[1];
    const int*   ei       = (const int*)d_in[2];
    const float* ew       = (const float*)d_in[3];
    const float* ru_param = (const float*)d_in[4];
    const float* ru_bias  = (const float*)d_in[5];
    const float* c_param  = (const float*)d_in[6];
    const float* c_bias   = (const float*)d_in[7];
    float* out = (float*)d_out;

    // preprocessing (counters are zero at entry: static init / previous tail)
    pre_kernel<<<DEG_BLOCKS + FEAT_BLOCKS, 256>>>(ei, ew, x, hs);
    scan_kernel<<<2, 1024>>>();
    scatter_kernel<<<DEG_BLOCKS, 256>>>(ei, ew);

    // conv1 Chebyshev propagations (full 1536 channels), fwd+bwd fused per launch
    prop_pair<false><<<dim3(NN, 2), 192>>>(0);   // x1f, x1b
    prop_pair<false><<<dim3(NN, 2), 192>>>(1);   // x2f, x2b

    // ru gates = sigmoid(cheb @ ru_param + bias)
    gemm_tc<128, true><<<MROWS / 128, 256>>>(ru_param, ru_bias, nullptr, nullptr);

    // conv2 order-0 hidden part: r*h (x-part of feat buffers reused from conv1)
    rh_kernel<<<(MROWS * 32 + 255) / 256, 256>>>(hs);

    // conv2 Chebyshev propagations (hidden 1024 channels only)
    prop_pair<true><<<dim3(NN, 2), 128>>>(0);
    prop_pair<true><<<dim3(NN, 2), 128>>>(1);

    // c = tanh(tanh(cheb @ c_param + bias));  out = u*h + (1-u)*c
    gemm_tc<64, false><<<MROWS / 128, 256>>>(c_param, c_bias, hs, out);

    // reset accumulators for the next call
    zero_tail_kernel<<<(NN + 255) / 256, 256>>>();
}

// round 6
// speedup vs baseline: 3.5665x; 1.0156x over previous
#include <cuda_runtime.h>
#include <cuda_fp16.h>
#include <cstdint>

#define NB   16
#define NN   10000
#define NE   320000
#define CIN  32
#define COUT 64
#define CC   96            // CIN + COUT
#define BC   1536          // NB*CC  (features per node, conv layout)
#define BC2  768           // half2 pairs per node row
#define BC4  192           // int4 per node row
#define MROWS 160000       // NN*NB

#define DEG_BLOCKS  1250           // NE/256
#define FEAT_PAIRS  (NN * BC / 2)
#define FEAT_BLOCKS (FEAT_PAIRS / 256)

// ---------------- static scratch (zero-init at load, re-zeroed at tail) ----------------
__device__ __align__(16) __half g_feat[5][NN * BC];   // x0, x1f, x1b, x2f, x2b (fp16)
__device__ float  g_u[MROWS * 64];          // update gate u (sigmoid), compact
__device__ float  g_deg_f[NN], g_deg_b[NN];
__device__ int    g_cnt_f[NN], g_cnt_b[NN];
__device__ int    g_cur_f[NN], g_cur_b[NN];
__device__ int    g_rp_f[NN + 1], g_rp_b[NN + 1];
__device__ int2   g_csr_f[NE], g_csr_b[NE]; // (neighbor, weight-as-bits)
__device__ int    g_any_odd;                // dtype sniff: 0 => edge_index is int64

__device__ __forceinline__ int load_node(const int* ei, int idx, int is64) {
    return is64 ? ei[2 * idx] : ei[idx];   // little-endian int64 low word
}

// ---------------- fused preprocessing: deg/cnt (+dtype detect) || build feat0 ----------------
__global__ void pre_kernel(const int* __restrict__ ei, const float* __restrict__ ew,
                           const float* __restrict__ x, const float* __restrict__ hs) {
    if (blockIdx.x < DEG_BLOCKS) {
        __shared__ int s_any;
        if (threadIdx.x == 0) s_any = 0;
        __syncthreads();
        int any = 0;
        for (int j = 2 * threadIdx.x + 1; j < 8192; j += 512) any |= ei[j];
        if (any) atomicOr(&s_any, 1);
        __syncthreads();
        int is64 = (s_any == 0);
        if (blockIdx.x == 0 && threadIdx.x == 0) g_any_odd = s_any;

        int e = blockIdx.x * 256 + threadIdx.x;
        int s = load_node(ei, e, is64);
        int d = load_node(ei, NE + e, is64);
        float w = ew[e];
        atomicAdd(&g_deg_f[s], w);
        atomicAdd(&g_deg_b[d], w);
        atomicAdd(&g_cnt_f[d], 1);
        atomicAdd(&g_cnt_b[s], 1);
    } else {
        int p = (blockIdx.x - DEG_BLOCKS) * 256 + threadIdx.x;  // half2 pair index
        int n = p / BC2;
        int rem = p - n * BC2;
        int c = 2 * rem;
        int b = c / CC;
        int cc = c - b * CC;
        float v0, v1;
        if (cc < CIN) {
            const float* xp = x + (size_t)(b * NN + n) * CIN + cc;
            v0 = xp[0]; v1 = xp[1];
        } else {
            const float* hp = hs + (size_t)(b * NN + n) * COUT + (cc - CIN);
            v0 = hp[0]; v1 = hp[1];
        }
        reinterpret_cast<__half2*>(g_feat[0])[p] = __float22half2_rn(make_float2(v0, v1));
    }
}

__global__ void scan_kernel() {
    const int* cnt = (blockIdx.x == 0) ? g_cnt_f : g_cnt_b;
    int* rp        = (blockIdx.x == 0) ? g_rp_f  : g_rp_b;
    __shared__ int sm[1024];
    __shared__ int s_carry;
    if (threadIdx.x == 0) s_carry = 0;
    __syncthreads();
    for (int base = 0; base < NN; base += 1024) {
        int i = base + threadIdx.x;
        int v = (i < NN) ? cnt[i] : 0;
        sm[threadIdx.x] = v;
        __syncthreads();
        for (int ofs = 1; ofs < 1024; ofs <<= 1) {
            int t = (threadIdx.x >= ofs) ? sm[threadIdx.x - ofs] : 0;
            __syncthreads();
            sm[threadIdx.x] += t;
            __syncthreads();
        }
        int carry = s_carry;
        if (i < NN) rp[i] = carry + sm[threadIdx.x] - v;
        __syncthreads();
        if (threadIdx.x == 1023) s_carry = carry + sm[1023];
        __syncthreads();
    }
    if (threadIdx.x == 0) rp[NN] = s_carry;
}

__global__ void scatter_kernel(const int* __restrict__ ei,
                               const float* __restrict__ ew) {
    int e = blockIdx.x * blockDim.x + threadIdx.x;
    if (e >= NE) return;
    int is64 = (g_any_odd == 0);
    int s = load_node(ei, e, is64);
    int d = load_node(ei, NE + e, is64);
    float w = ew[e];
    float wf = w / g_deg_f[s];
    float wb = w / g_deg_b[d];
    int p = atomicAdd(&g_cur_f[d], 1);
    g_csr_f[g_rp_f[d] + p] = make_int2(s, __float_as_int(wf));
    int q = atomicAdd(&g_cur_b[s], 1);
    g_csr_b[g_rp_b[s] + q] = make_int2(d, __float_as_int(wb));
}

// ---------------- propagation: 16 channels/thread (2 int4), fwd+bwd via blockIdx.y ----------------
__device__ __forceinline__ void acc8(float* a, int4 v, float w) {
    const __half2* h = reinterpret_cast<const __half2*>(&v);
#pragma unroll
    for (int q = 0; q < 4; q++) {
        float2 f = __half22float2(h[q]);
        a[2 * q]     += w * f.x;
        a[2 * q + 1] += w * f.y;
    }
}

__device__ __forceinline__ int4 pack8(const float* a) {
    int4 ov;
    __half2* oh = reinterpret_cast<__half2*>(&ov);
#pragma unroll
    for (int q = 0; q < 4; q++)
        oh[q] = __float22half2_rn(make_float2(a[2 * q], a[2 * q + 1]));
    return ov;
}

// stage 0: feat[1+dir] = P_dir feat0
// stage 1: feat[3+dir] = 2 P_dir feat[1+dir] - feat0
// NT threads/node; each thread owns int4 slots q0=t, q1=t+NT (HONLY remaps to hidden slots)
template <bool HONLY>
__global__ void __launch_bounds__(96) prop_pair(int stage) {
    constexpr int NT = HONLY ? 64 : 96;
    int dir = blockIdx.y;
    int in_idx  = (stage == 0) ? 0 : 1 + dir;
    int out_idx = (stage == 0) ? 1 + dir : 3 + dir;

    const int4* __restrict__ in  = reinterpret_cast<const int4*>(g_feat[in_idx]);
    int4* __restrict__ out       = reinterpret_cast<int4*>(g_feat[out_idx]);
    const int* __restrict__ rp   = dir ? g_rp_b : g_rp_f;
    const int2* __restrict__ csr = dir ? g_csr_b : g_csr_f;

    int node = blockIdx.x;
    int t = threadIdx.x;
    int q0 = t, q1 = t + NT;
    int idx0 = HONLY ? ((q0 >> 3) * 12 + 4 + (q0 & 7)) : q0;
    int idx1 = HONLY ? ((q1 >> 3) * 12 + 4 + (q1 & 7)) : q1;

    int s = rp[node];
    int e = rp[node + 1];
    float a0[8], a1[8];
#pragma unroll
    for (int q = 0; q < 8; q++) { a0[q] = 0.f; a1[q] = 0.f; }

    int i = s;
    for (; i + 1 < e; i += 2) {
        int2 e0 = __ldg(&csr[i]);
        int2 e1 = __ldg(&csr[i + 1]);
        const int4* p0 = in + e0.x * BC4;
        const int4* p1 = in + e1.x * BC4;
        int4 v00 = __ldg(p0 + idx0);
        int4 v01 = __ldg(p0 + idx1);
        int4 v10 = __ldg(p1 + idx0);
        int4 v11 = __ldg(p1 + idx1);
        float w0 = __int_as_float(e0.y);
        float w1 = __int_as_float(e1.y);
        acc8(a0, v00, w0); acc8(a1, v01, w0);
        acc8(a0, v10, w1); acc8(a1, v11, w1);
    }
    if (i < e) {
        int2 ed = __ldg(&csr[i]);
        const int4* p0 = in + ed.x * BC4;
        float w = __int_as_float(ed.y);
        acc8(a0, __ldg(p0 + idx0), w);
        acc8(a1, __ldg(p0 + idx1), w);
    }

    if (stage == 1) {
        const int4* b = reinterpret_cast<const int4*>(g_feat[0]) + node * BC4;
        int4 b0 = b[idx0], b1 = b[idx1];
        const __half2* h0 = reinterpret_cast<const __half2*>(&b0);
        const __half2* h1 = reinterpret_cast<const __half2*>(&b1);
#pragma unroll
        for (int q = 0; q < 4; q++) {
            float2 f0 = __half22float2(h0[q]);
            float2 f1 = __half22float2(h1[q]);
            a0[2 * q]     = 2.f * a0[2 * q]     - f0.x;
            a0[2 * q + 1] = 2.f * a0[2 * q + 1] - f0.y;
            a1[2 * q]     = 2.f * a1[2 * q]     - f1.x;
            a1[2 * q + 1] = 2.f * a1[2 * q + 1] - f1.y;
        }
    }
    out[node * BC4 + idx0] = pack8(a0);
    out[node * BC4 + idx1] = pack8(a1);
}

// ---------------- tensor-core GEMM: fp16 mma.m16n8k16, fp32 accumulate ----------------
// out(M=160000, NOUT) = sum_l A_l(160000,96) @ W_l(96,NOUT)
// ru epilogue: cols<64 -> r*h written to feat0 hidden slots (fp16); cols>=64 -> u to g_u.
// c  epilogue: out = u*h + (1-u)*tanh(tanh(v)).
template <int NOUT, bool ISRU>
__global__ void __launch_bounds__(256) gemm_tc(const float* __restrict__ Wp,
                                               const float* __restrict__ bias,
                                               const float* __restrict__ hs,
                                               float* __restrict__ dout) {
    constexpr int WN = NOUT / 2;
    constexpr int NF = WN / 8;
    constexpr int ASTRIDE = 104;   // halves per A smem row
    constexpr int BSTRIDE = 102;   // halves per B smem row

    __shared__ __align__(16) __half As[128 * ASTRIDE];
    __shared__ __align__(4)  __half Bs[NOUT * BSTRIDE];

    int tid  = threadIdx.x;
    int w    = tid >> 5;
    int lane = tid & 31;
    int wm   = w >> 1;
    int wn   = w & 1;
    int g    = lane >> 2;
    int t    = lane & 3;
    int mRow = blockIdx.x * 128;

    const uint32_t* Aw = reinterpret_cast<const uint32_t*>(As);
    const uint32_t* Bw = reinterpret_cast<const uint32_t*>(Bs);

    float acc[2][NF][4];
#pragma unroll
    for (int mf = 0; mf < 2; mf++)
#pragma unroll
        for (int nf = 0; nf < NF; nf++)
#pragma unroll
            for (int j = 0; j < 4; j++) acc[mf][nf][j] = 0.f;

#pragma unroll 1
    for (int l = 0; l < 5; ++l) {
        __syncthreads();
        const int4* Ag = reinterpret_cast<const int4*>(g_feat[l]) + (size_t)mRow * 12;
#pragma unroll
        for (int j = 0; j < 6; j++) {
            int id = j * 256 + tid;
            int r = id / 12, c = id % 12;
            *reinterpret_cast<int4*>(&As[r * ASTRIDE + c * 8]) = __ldg(&Ag[r * 12 + c]);
        }
        {
            constexpr int KSTEP = 256 / NOUT;
            int n = tid % NOUT;
            int kb = tid / NOUT;
#pragma unroll
            for (int k = kb; k < CC; k += KSTEP)
                Bs[n * BSTRIDE + k] = __float2half(__ldg(&Wp[((size_t)k * 5 + l) * NOUT + n]));
        }
        __syncthreads();

#pragma unroll
        for (int ks = 0; ks < 6; ks++) {
            uint32_t a[2][4];
#pragma unroll
            for (int mf = 0; mf < 2; mf++) {
                int base = (wm * 32 + mf * 16 + g) * (ASTRIDE / 2) + ks * 8 + t;
                a[mf][0] = Aw[base];
                a[mf][1] = Aw[base + 8 * (ASTRIDE / 2)];
                a[mf][2] = Aw[base + 4];
                a[mf][3] = Aw[base + 8 * (ASTRIDE / 2) + 4];
            }
            uint32_t b[NF][2];
#pragma unroll
            for (int nf = 0; nf < NF; nf++) {
                int col = wn * WN + nf * 8 + g;
                int bb = col * (BSTRIDE / 2) + ks * 8 + t;
                b[nf][0] = Bw[bb];
                b[nf][1] = Bw[bb + 4];
            }
#pragma unroll
            for (int mf = 0; mf < 2; mf++)
#pragma unroll
                for (int nf = 0; nf < NF; nf++) {
                    asm volatile(
                        "mma.sync.aligned.m16n8k16.row.col.f32.f16.f16.f32 "
                        "{%0,%1,%2,%3}, {%4,%5,%6,%7}, {%8,%9}, {%0,%1,%2,%3};"
                        : "+f"(acc[mf][nf][0]), "+f"(acc[mf][nf][1]),
                          "+f"(acc[mf][nf][2]), "+f"(acc[mf][nf][3])
                        : "r"(a[mf][0]), "r"(a[mf][1]), "r"(a[mf][2]), "r"(a[mf][3]),
                          "r"(b[nf][0]), "r"(b[nf][1]));
                }
        }
    }

    // epilogue: fragment j pairs (2t, 2t+1) in cols; jr in {0,1} selects row g / g+8
#pragma unroll
    for (int mf = 0; mf < 2; mf++) {
        int r0 = mRow + wm * 32 + mf * 16 + g;
#pragma unroll
        for (int nf = 0; nf < NF; nf++) {
            int c0 = wn * WN + nf * 8 + 2 * t;
#pragma unroll
            for (int jr = 0; jr < 2; jr++) {
                int row = r0 + jr * 8;              // n*16 + b
                int n = row >> 4;
                int b = row & 15;
                float v0 = acc[mf][nf][jr * 2]     + bias[c0];
                float v1 = acc[mf][nf][jr * 2 + 1] + bias[c0 + 1];
                if (ISRU) {
                    float s0 = 1.f / (1.f + expf(-v0));
                    float s1 = 1.f / (1.f + expf(-v1));
                    if (c0 < COUT) {            // r: write r*h into feat0 hidden slots
                        float2 h = *reinterpret_cast<const float2*>(
                            &hs[(b * NN + n) * COUT + c0]);
                        *reinterpret_cast<__half2*>(&g_feat[0][n * BC + b * CC + CIN + c0]) =
                            __float22half2_rn(make_float2(s0 * h.x, s1 * h.y));
                    } else {                    // u: compact buffer
                        *reinterpret_cast<float2*>(&g_u[row * 64 + (c0 - COUT)]) =
                            make_float2(s0, s1);
                    }
                } else {
                    float cv0 = tanhf(tanhf(v0));
                    float cv1 = tanhf(tanhf(v1));
                    float2 u = *reinterpret_cast<const float2*>(&g_u[row * 64 + c0]);
                    float2 h = *reinterpret_cast<const float2*>(
                        &hs[(b * NN + n) * COUT + c0]);
                    *reinterpret_cast<float2*>(&dout[(b * NN + n) * COUT + c0]) =
                        make_float2(u.x * h.x + (1.f - u.x) * cv0,
                                    u.y * h.y + (1.f - u.y) * cv1);
                }
            }
        }
    }
}

// tail reset so the next kernel_launch call sees zeroed accumulators
__global__ void zero_tail_kernel() {
    int i = blockIdx.x * blockDim.x + threadIdx.x;
    if (i < NN) {
        g_deg_f[i] = 0.f; g_deg_b[i] = 0.f;
        g_cnt_f[i] = 0;   g_cnt_b[i] = 0;
        g_cur_f[i] = 0;   g_cur_b[i] = 0;
    }
}

// ---------------- launch ----------------
extern "C" void kernel_launch(void* const* d_in, const int* in_sizes, int n_in,
                              void* d_out, int out_size) {
    const float* x        = (const float*)d_in[0];
    const float* hs       = (const float*)d_in[1];
    const int*   ei       = (const int*)d_in[2];
    const float* ew       = (const float*)d_in[3];
    const float* ru_param = (const float*)d_in[4];
    const float* ru_bias  = (const float*)d_in[5];
    const float* c_param  = (const float*)d_in[6];
    const float* c_bias   = (const float*)d_in[7];
    float* out = (float*)d_out;

    // preprocessing (counters are zero at entry: static init / previous tail)
    pre_kernel<<<DEG_BLOCKS + FEAT_BLOCKS, 256>>>(ei, ew, x, hs);
    scan_kernel<<<2, 1024>>>();
    scatter_kernel<<<DEG_BLOCKS, 256>>>(ei, ew);

    // conv1 Chebyshev propagations (full 1536 channels), fwd+bwd fused per launch
    prop_pair<false><<<dim3(NN, 2), 96>>>(0);   // x1f, x1b
    prop_pair<false><<<dim3(NN, 2), 96>>>(1);   // x2f, x2b

    // ru gates; epilogue writes r*h into feat0 hidden slots and u into g_u
    gemm_tc<128, true><<<MROWS / 128, 256>>>(ru_param, ru_bias, hs, nullptr);

    // conv2 Chebyshev propagations (hidden 1024 channels only)
    prop_pair<true><<<dim3(NN, 2), 64>>>(0);
    prop_pair<true><<<dim3(NN, 2), 64>>>(1);

    // c = tanh(tanh(cheb @ c_param + bias));  out = u*h + (1-u)*c
    gemm_tc<64, false><<<MROWS / 128, 256>>>(c_param, c_bias, hs, out);

    // reset accumulators for the next call
    zero_tail_kernel<<<(NN + 255) / 256, 256>>>();
}